// round 15
// baseline (speedup 1.0000x reference)
#include <cuda_runtime.h>
#include <cuda_fp16.h>
#include <cstdint>

#define TT 8192
#define HD 1024
#define NE 8
#define NKT 32            // 1024 / BK
#define STAGE 16384       // 8KB A + 8KB B per stage (BK=32)
#define NCTA 296          // 2 CTAs/SM x 148 SMs (persistent)

// ---- scratch (device globals; no allocations allowed) ----------------------
__device__ int    g_counts[NE];
__device__ int    g_work;                  // persistent work counter
__device__ int    g_tok[NE * TT];          // slot -> token*2 + choice (-1 pad)
__device__ float  g_tws[2 * TT];           // (token,choice) -> combine weight
__device__ __half g_xh[(size_t)TT * HD];
__device__ __half g_wh[(size_t)NE * HD * HD];
__device__ __half g_part[(size_t)2 * TT * HD];   // fp16 partial rows

// ---- PTX helpers (baseline compute_103-safe) -------------------------------
__device__ __forceinline__ uint32_t smem_u32(const void* p) {
    uint32_t a;
    asm("{ .reg .u64 t; cvta.to.shared.u64 t, %1; cvt.u32.u64 %0, t; }"
        : "=r"(a) : "l"(p));
    return a;
}
#define CP16(dst, src) \
    asm volatile("cp.async.cg.shared.global [%0], [%1], 16;" :: "r"(dst), "l"(src))
#define CP_COMMIT() asm volatile("cp.async.commit_group;" ::: "memory")
#define CP_WAIT2()  asm volatile("cp.async.wait_group 2;" ::: "memory")
#define CP_WAIT0()  asm volatile("cp.async.wait_group 0;" ::: "memory")

__device__ __forceinline__ void ldsm4(uint32_t* r, uint32_t a) {
    asm volatile("ldmatrix.sync.aligned.m8n8.x4.shared.b16 {%0,%1,%2,%3}, [%4];"
                 : "=r"(r[0]), "=r"(r[1]), "=r"(r[2]), "=r"(r[3]) : "r"(a));
}
__device__ __forceinline__ void mma16816(float* c, const uint32_t* a, const uint32_t* b) {
    asm volatile(
        "mma.sync.aligned.m16n8k16.row.col.f32.f16.f16.f32 "
        "{%0,%1,%2,%3}, {%4,%5,%6,%7}, {%8,%9}, {%0,%1,%2,%3};"
        : "+f"(c[0]), "+f"(c[1]), "+f"(c[2]), "+f"(c[3])
        : "r"(a[0]), "r"(a[1]), "r"(a[2]), "r"(a[3]), "r"(b[0]), "r"(b[1]));
}

// swizzled 16B-chunk offset within a tile of 64B rows (4 chunks/row, BK=32)
__device__ __forceinline__ uint32_t swz64(int row, int chunk) {
    return (uint32_t)(row * 64 + ((chunk ^ ((row >> 1) & 3)) << 4));
}

// ---------------------------------------------------------------------------
// expert_w fp32 -> fp16 (+ zero counters & work counter, block 0)
__global__ void k_convw(const float* __restrict__ w) {
    if (blockIdx.x == 0 && threadIdx.x < NE + 1) {
        if (threadIdx.x < NE) g_counts[threadIdx.x] = 0;
        else g_work = 0;
    }
    size_t i = ((size_t)blockIdx.x * blockDim.x + threadIdx.x) * 4;
    float4 v = *(const float4*)(w + i);
    __half2* p = (__half2*)(g_wh + i);
    p[0] = __floats2half2_rn(v.x, v.y);
    p[1] = __floats2half2_rn(v.z, v.w);
}

// Router + fp16 cast of x. 32 tokens per block (4 per warp) to amortize the
// smem preload of router_w.
__global__ void __launch_bounds__(256)
k_router(const float* __restrict__ x,
         const float* __restrict__ rw,
         const float* __restrict__ rb) {
    __shared__ float s_rw[NE * HD];
    __shared__ float s_rb[NE];
    int tid = threadIdx.x;
    for (int i = tid; i < NE * HD; i += blockDim.x) s_rw[i] = rw[i];
    if (tid < NE) s_rb[tid] = rb[tid];
    __syncthreads();

    int warp = tid >> 5, lane = tid & 31;

#pragma unroll 1
    for (int rep = 0; rep < 4; rep++) {
        int t = blockIdx.x * 32 + warp * 4 + rep;
        const float* xr = x + (size_t)t * HD;

        float xv[32];
#pragma unroll
        for (int i = 0; i < 32; i++) xv[i] = xr[lane + 32 * i];

        __half* xh = g_xh + (size_t)t * HD;
#pragma unroll
        for (int i = 0; i < 32; i++) xh[lane + 32 * i] = __float2half_rn(xv[i]);

        float sc[NE];
#pragma unroll
        for (int e = 0; e < NE; e++) {
            float s = 0.0f;
            const float* wr = s_rw + e * HD;
#pragma unroll
            for (int i = 0; i < 32; i++) s += xv[i] * wr[lane + 32 * i];
#pragma unroll
            for (int o = 16; o > 0; o >>= 1) s += __shfl_xor_sync(0xffffffffu, s, o);
            sc[e] = s + s_rb[e];
        }

        if (lane == 0) {
            int e0 = 0;
#pragma unroll
            for (int e = 1; e < NE; e++) if (sc[e] > sc[e0]) e0 = e;
            int e1 = (e0 == 0) ? 1 : 0;
#pragma unroll
            for (int e = 0; e < NE; e++) if (e != e1 && e != e0 && sc[e] > sc[e1]) e1 = e;

            float d  = __expf(sc[e1] - sc[e0]);   // <= 1, stable
            float w0 = 1.0f / (1.0f + d);
            g_tws[2 * t]     = w0;
            g_tws[2 * t + 1] = 1.0f - w0;
            int p0 = atomicAdd(&g_counts[e0], 1);
            g_tok[e0 * TT + p0] = t * 2;
            int p1 = atomicAdd(&g_counts[e1], 1);
            g_tok[e1 * TT + p1] = t * 2 + 1;
        }
    }
}

// ---------------------------------------------------------------------------
// Persistent grouped GEMM: 296 CTAs, work-stealing over (expert, mtile, ntile).
// Per tile: 128x128, BK=32, 8 warps (2x4), warp tile 64x32, 4-stage cp.async,
// one __syncthreads per ktile. All 12 ldsm4 of a ktile hoisted ahead of the
// 16 mma to hide LDS latency. fp16 partial epilogue.
// ---------------------------------------------------------------------------
__global__ void __launch_bounds__(256, 2)
k_gemm(const float* __restrict__ eb) {
    __shared__ int   s_work;
    __shared__ int   s_tok[128];
    __shared__ float s_bias[128];
    extern __shared__ __align__(128) char dsm[];   // 4 x (A 8KB | B 8KB)

    int tid = threadIdx.x, lane = tid & 31, wid = tid >> 5;

    // per-expert tile prefix sums (registers, identical across threads)
    int pfx[NE + 1];
    pfx[0] = 0;
#pragma unroll
    for (int e = 0; e < NE; e++)
        pfx[e + 1] = pfx[e] + ((g_counts[e] + 127) >> 7);
    int total = pfx[NE] * 8;

    uint32_t sbase = smem_u32(dsm);

    // fixed compute mapping: 2x4 warps, warp tile 64x32
    int wm = (wid >> 2) * 64, wn = (wid & 3) * 32;
    int ha = lane >> 4;
    int hb = (lane >> 3) & 1;
    int sxa = ((lane & 15) >> 1) & 3;
    int sxb = (((((lane >> 4) << 3) + (lane & 7))) >> 1) & 3;
    uint32_t arow = (uint32_t)(wm + (lane & 15)) * 64u;
    uint32_t brow = (uint32_t)(wn + ((lane >> 4) << 3) + (lane & 7)) * 64u;

    // fixed loader mapping pieces
    int lr = tid >> 1;
    int lc = (tid & 1) * 2;
    uint32_t sa0 = swz64(lr, lc), sa1 = swz64(lr, lc + 1);

    for (;;) {
        if (tid == 0) s_work = atomicAdd(&g_work, 1);
        __syncthreads();                       // also protects s_tok reuse
        int s = s_work;
        if (s >= total) break;

        int mg = s >> 3, ntile = s & 7;
        int e = 0;
#pragma unroll
        for (int q = 0; q < NE - 1; q++) if (mg >= pfx[q + 1]) e = q + 1;
        int cnt = g_counts[e];
        int m0  = (mg - pfx[e]) * 128;
        int n0  = ntile * 128;

        if (tid < 128) {
            int m = m0 + tid;
            s_tok[tid]  = (m < cnt) ? g_tok[e * TT + m] : -1;
            s_bias[tid] = eb[e * HD + n0 + tid];
        }
        __syncthreads();

        int v   = s_tok[lr];
        int tok = (v < 0 ? 0 : v) >> 1;
        const char* ga = (const char*)(g_xh + (size_t)tok * HD) + lc * 16;
        const char* gb = (const char*)(g_wh + (size_t)e * HD * HD
                                            + (size_t)(n0 + lr) * HD) + lc * 16;

        auto issue = [&](int kt) {
            uint32_t ab = sbase + (uint32_t)(kt & 3) * STAGE;
            uint32_t bb = ab + 8192u;
            const char* a = ga + kt * 64;
            const char* b = gb + kt * 64;
            CP16(ab + sa0, a);
            CP16(ab + sa1, a + 16);
            CP16(bb + sa0, b);
            CP16(bb + sa1, b + 16);
        };

        float acc[4][4][4];
#pragma unroll
        for (int mt = 0; mt < 4; mt++)
#pragma unroll
            for (int nt = 0; nt < 4; nt++)
#pragma unroll
                for (int j = 0; j < 4; j++) acc[mt][nt][j] = 0.0f;

        issue(0); CP_COMMIT();
        issue(1); CP_COMMIT();
        issue(2); CP_COMMIT();

        for (int kt = 0; kt < NKT; kt++) {
            CP_WAIT2();
            __syncthreads();
            if (kt + 3 < NKT) issue(kt + 3);
            CP_COMMIT();

            uint32_t ab = sbase + (uint32_t)(kt & 3) * STAGE;
            uint32_t bb = ab + 8192u;
            uint32_t abase = ab + arow;
            uint32_t bbase = bb + brow;

            // hoist ALL fragment loads for this ktile before any mma
            uint32_t ar[2][4][4], br[2][2][4];
#pragma unroll
            for (int ks = 0; ks < 2; ks++) {
                uint32_t ca = (uint32_t)(((ks * 2 + ha) ^ sxa) << 4);
                uint32_t cb = (uint32_t)(((ks * 2 + hb) ^ sxb) << 4);
#pragma unroll
                for (int mt = 0; mt < 4; mt++)
                    ldsm4(ar[ks][mt], abase + mt * 1024 + ca);
#pragma unroll
                for (int q = 0; q < 2; q++)
                    ldsm4(br[ks][q], bbase + q * 1024 + cb);
            }
#pragma unroll
            for (int ks = 0; ks < 2; ks++)
#pragma unroll
                for (int mt = 0; mt < 4; mt++)
#pragma unroll
                    for (int q = 0; q < 2; q++) {
                        mma16816(acc[mt][2 * q],     ar[ks][mt], &br[ks][q][0]);
                        mma16816(acc[mt][2 * q + 1], ar[ks][mt], &br[ks][q][2]);
                    }
        }
        CP_WAIT0();    // drain before next tile reuses stage buffers

        // epilogue: + bias, store fp16 partial rows
#pragma unroll
        for (int mt = 0; mt < 4; mt++) {
#pragma unroll
            for (int h = 0; h < 2; h++) {
                int row = wm + mt * 16 + (lane >> 2) + h * 8;
                int vv  = s_tok[row];
                if (vv >= 0) {
                    __half* prow = g_part + (size_t)vv * HD + n0;
#pragma unroll
                    for (int nt = 0; nt < 4; nt++) {
                        int c = wn + nt * 8 + (lane & 3) * 2;
                        *(__half2*)(prow + c) = __floats2half2_rn(
                            acc[mt][nt][2 * h]     + s_bias[c],
                            acc[mt][nt][2 * h + 1] + s_bias[c + 1]);
                    }
                }
            }
        }
    }
}

// out[t] = w0 * part[2t] + w1 * part[2t+1]
__global__ void k_combine(float* __restrict__ out) {
    int t = blockIdx.x, tid = threadIdx.x;
    float w0 = g_tws[2 * t], w1 = g_tws[2 * t + 1];
    const __half2* p0 = (const __half2*)(g_part + (size_t)(2 * t) * HD);
    const __half2* p1 = (const __half2*)(g_part + (size_t)(2 * t + 1) * HD);
    float2 a0 = __half22float2(p0[2 * tid]);
    float2 a1 = __half22float2(p0[2 * tid + 1]);
    float2 b0 = __half22float2(p1[2 * tid]);
    float2 b1 = __half22float2(p1[2 * tid + 1]);
    float4 o;
    o.x = w0 * a0.x + w1 * b0.x;
    o.y = w0 * a0.y + w1 * b0.y;
    o.z = w0 * a1.x + w1 * b1.x;
    o.w = w0 * a1.y + w1 * b1.y;
    ((float4*)(out + (size_t)t * HD))[tid] = o;
}

// ---------------------------------------------------------------------------
extern "C" void kernel_launch(void* const* d_in, const int* in_sizes, int n_in,
                              void* d_out, int out_size) {
    const float* x  = (const float*)d_in[0];
    const float* rw = (const float*)d_in[1];
    const float* rb = (const float*)d_in[2];
    const float* ew = (const float*)d_in[3];
    const float* eb = (const float*)d_in[4];
    float* out = (float*)d_out;

    const int DSM = 4 * STAGE;    // 65536
    static int done = 0;
    if (!done) {
        cudaFuncSetAttribute(k_gemm, cudaFuncAttributeMaxDynamicSharedMemorySize, DSM);
        done = 1;
    }

    k_convw<<<(NE * HD * HD) / 1024, 256>>>(ew);
    k_router<<<TT / 32, 256>>>(x, rw, rb);
    k_gemm<<<NCTA, 256, DSM>>>(eb);
    k_combine<<<TT, 256>>>(out);
}

// round 16
// speedup vs baseline: 1.0370x; 1.0370x over previous
#include <cuda_runtime.h>
#include <cuda_fp16.h>
#include <cstdint>

#define TT 8192
#define HD 1024
#define NE 8
#define NKT 32            // 1024 / BK
#define STAGE 16384       // 8KB A + 8KB B per stage (BK=32)
#define NCTA 296          // 2 CTAs/SM x 148 SMs (persistent)

// ---- scratch (device globals; no allocations allowed) ----------------------
__device__ int    g_counts[NE];
__device__ int    g_work;                  // persistent work counter
__device__ int    g_tok[NE * TT];          // slot -> token*2 + choice (-1 pad)
__device__ float  g_tws[2 * TT];           // (token,choice) -> combine weight
__device__ __half g_xh[(size_t)TT * HD];
__device__ __half g_wh[(size_t)NE * HD * HD];
__device__ __half g_part[(size_t)2 * TT * HD];   // fp16 partial rows

// ---- PTX helpers (baseline compute_103-safe) -------------------------------
__device__ __forceinline__ uint32_t smem_u32(const void* p) {
    uint32_t a;
    asm("{ .reg .u64 t; cvta.to.shared.u64 t, %1; cvt.u32.u64 %0, t; }"
        : "=r"(a) : "l"(p));
    return a;
}
#define CP16(dst, src) \
    asm volatile("cp.async.cg.shared.global [%0], [%1], 16;" :: "r"(dst), "l"(src))
#define CP_COMMIT() asm volatile("cp.async.commit_group;" ::: "memory")
#define CP_WAIT2()  asm volatile("cp.async.wait_group 2;" ::: "memory")
#define CP_WAIT0()  asm volatile("cp.async.wait_group 0;" ::: "memory")

__device__ __forceinline__ void ldsm4(uint32_t* r, uint32_t a) {
    asm volatile("ldmatrix.sync.aligned.m8n8.x4.shared.b16 {%0,%1,%2,%3}, [%4];"
                 : "=r"(r[0]), "=r"(r[1]), "=r"(r[2]), "=r"(r[3]) : "r"(a));
}
__device__ __forceinline__ void mma16816(float* c, const uint32_t* a, const uint32_t* b) {
    asm volatile(
        "mma.sync.aligned.m16n8k16.row.col.f32.f16.f16.f32 "
        "{%0,%1,%2,%3}, {%4,%5,%6,%7}, {%8,%9}, {%0,%1,%2,%3};"
        : "+f"(c[0]), "+f"(c[1]), "+f"(c[2]), "+f"(c[3])
        : "r"(a[0]), "r"(a[1]), "r"(a[2]), "r"(a[3]), "r"(b[0]), "r"(b[1]));
}

// swizzled 16B-chunk offset within a tile of 64B rows (4 chunks/row, BK=32)
__device__ __forceinline__ uint32_t swz64(int row, int chunk) {
    return (uint32_t)(row * 64 + ((chunk ^ ((row >> 1) & 3)) << 4));
}

// ---------------------------------------------------------------------------
// expert_w fp32 -> fp16 (+ zero counters & work counter, block 0)
__global__ void k_convw(const float* __restrict__ w) {
    if (blockIdx.x == 0 && threadIdx.x < NE + 1) {
        if (threadIdx.x < NE) g_counts[threadIdx.x] = 0;
        else g_work = 0;
    }
    size_t i = ((size_t)blockIdx.x * blockDim.x + threadIdx.x) * 4;
    float4 v = *(const float4*)(w + i);
    __half2* p = (__half2*)(g_wh + i);
    p[0] = __floats2half2_rn(v.x, v.y);
    p[1] = __floats2half2_rn(v.z, v.w);
}

// Router + fp16 cast of x. 32 tokens per block (4 per warp) to amortize the
// smem preload of router_w.
__global__ void __launch_bounds__(256)
k_router(const float* __restrict__ x,
         const float* __restrict__ rw,
         const float* __restrict__ rb) {
    __shared__ float s_rw[NE * HD];
    __shared__ float s_rb[NE];
    int tid = threadIdx.x;
    for (int i = tid; i < NE * HD; i += blockDim.x) s_rw[i] = rw[i];
    if (tid < NE) s_rb[tid] = rb[tid];
    __syncthreads();

    int warp = tid >> 5, lane = tid & 31;

#pragma unroll 1
    for (int rep = 0; rep < 4; rep++) {
        int t = blockIdx.x * 32 + warp * 4 + rep;
        const float* xr = x + (size_t)t * HD;

        float xv[32];
#pragma unroll
        for (int i = 0; i < 32; i++) xv[i] = xr[lane + 32 * i];

        __half* xh = g_xh + (size_t)t * HD;
#pragma unroll
        for (int i = 0; i < 32; i++) xh[lane + 32 * i] = __float2half_rn(xv[i]);

        float sc[NE];
#pragma unroll
        for (int e = 0; e < NE; e++) {
            float s = 0.0f;
            const float* wr = s_rw + e * HD;
#pragma unroll
            for (int i = 0; i < 32; i++) s += xv[i] * wr[lane + 32 * i];
#pragma unroll
            for (int o = 16; o > 0; o >>= 1) s += __shfl_xor_sync(0xffffffffu, s, o);
            sc[e] = s + s_rb[e];
        }

        if (lane == 0) {
            int e0 = 0;
#pragma unroll
            for (int e = 1; e < NE; e++) if (sc[e] > sc[e0]) e0 = e;
            int e1 = (e0 == 0) ? 1 : 0;
#pragma unroll
            for (int e = 0; e < NE; e++) if (e != e1 && e != e0 && sc[e] > sc[e1]) e1 = e;

            float d  = __expf(sc[e1] - sc[e0]);   // <= 1, stable
            float w0 = 1.0f / (1.0f + d);
            g_tws[2 * t]     = w0;
            g_tws[2 * t + 1] = 1.0f - w0;
            int p0 = atomicAdd(&g_counts[e0], 1);
            g_tok[e0 * TT + p0] = t * 2;
            int p1 = atomicAdd(&g_counts[e1], 1);
            g_tok[e1 * TT + p1] = t * 2 + 1;
        }
    }
}

// ---------------------------------------------------------------------------
// Persistent grouped GEMM: 296 CTAs, work-stealing over (expert, mtile, ntile).
// Per tile: 128x128, BK=32, 8 warps (2x4), warp tile 64x32, 4-stage cp.async,
// one __syncthreads per ktile, interleaved ldsm/mma (R13 exact). fp16 epilogue.
// ---------------------------------------------------------------------------
__global__ void __launch_bounds__(256, 2)
k_gemm(const float* __restrict__ eb) {
    __shared__ int   s_work;
    __shared__ int   s_tok[128];
    __shared__ float s_bias[128];
    extern __shared__ __align__(128) char dsm[];   // 4 x (A 8KB | B 8KB)

    int tid = threadIdx.x, lane = tid & 31, wid = tid >> 5;

    // per-expert tile prefix sums (registers, identical across threads)
    int pfx[NE + 1];
    pfx[0] = 0;
#pragma unroll
    for (int e = 0; e < NE; e++)
        pfx[e + 1] = pfx[e] + ((g_counts[e] + 127) >> 7);
    int total = pfx[NE] * 8;

    uint32_t sbase = smem_u32(dsm);

    // fixed compute mapping: 2x4 warps, warp tile 64x32
    int wm = (wid >> 2) * 64, wn = (wid & 3) * 32;
    int ha = lane >> 4;
    int hb = (lane >> 3) & 1;
    int sxa = ((lane & 15) >> 1) & 3;
    int sxb = (((((lane >> 4) << 3) + (lane & 7))) >> 1) & 3;
    uint32_t arow = (uint32_t)(wm + (lane & 15)) * 64u;
    uint32_t brow = (uint32_t)(wn + ((lane >> 4) << 3) + (lane & 7)) * 64u;

    // fixed loader mapping pieces
    int lr = tid >> 1;
    int lc = (tid & 1) * 2;
    uint32_t sa0 = swz64(lr, lc), sa1 = swz64(lr, lc + 1);

    for (;;) {
        if (tid == 0) s_work = atomicAdd(&g_work, 1);
        __syncthreads();                       // also protects s_tok reuse
        int s = s_work;
        if (s >= total) break;

        int mg = s >> 3, ntile = s & 7;
        int e = 0;
#pragma unroll
        for (int q = 0; q < NE - 1; q++) if (mg >= pfx[q + 1]) e = q + 1;
        int cnt = g_counts[e];
        int m0  = (mg - pfx[e]) * 128;
        int n0  = ntile * 128;

        if (tid < 128) {
            int m = m0 + tid;
            s_tok[tid]  = (m < cnt) ? g_tok[e * TT + m] : -1;
            s_bias[tid] = eb[e * HD + n0 + tid];
        }
        __syncthreads();

        int v   = s_tok[lr];
        int tok = (v < 0 ? 0 : v) >> 1;
        const char* ga = (const char*)(g_xh + (size_t)tok * HD) + lc * 16;
        const char* gb = (const char*)(g_wh + (size_t)e * HD * HD
                                            + (size_t)(n0 + lr) * HD) + lc * 16;

        auto issue = [&](int kt) {
            uint32_t ab = sbase + (uint32_t)(kt & 3) * STAGE;
            uint32_t bb = ab + 8192u;
            const char* a = ga + kt * 64;
            const char* b = gb + kt * 64;
            CP16(ab + sa0, a);
            CP16(ab + sa1, a + 16);
            CP16(bb + sa0, b);
            CP16(bb + sa1, b + 16);
        };

        float acc[4][4][4];
#pragma unroll
        for (int mt = 0; mt < 4; mt++)
#pragma unroll
            for (int nt = 0; nt < 4; nt++)
#pragma unroll
                for (int j = 0; j < 4; j++) acc[mt][nt][j] = 0.0f;

        issue(0); CP_COMMIT();
        issue(1); CP_COMMIT();
        issue(2); CP_COMMIT();

        for (int kt = 0; kt < NKT; kt++) {
            CP_WAIT2();
            __syncthreads();
            if (kt + 3 < NKT) issue(kt + 3);
            CP_COMMIT();

            uint32_t ab = sbase + (uint32_t)(kt & 3) * STAGE;
            uint32_t bb = ab + 8192u;
            uint32_t abase = ab + arow;
            uint32_t bbase = bb + brow;
#pragma unroll
            for (int ks = 0; ks < 2; ks++) {
                uint32_t ca = (uint32_t)(((ks * 2 + ha) ^ sxa) << 4);
                uint32_t cb = (uint32_t)(((ks * 2 + hb) ^ sxb) << 4);
                uint32_t ar[4][4], br[2][4];
#pragma unroll
                for (int mt = 0; mt < 4; mt++) ldsm4(ar[mt], abase + mt * 1024 + ca);
#pragma unroll
                for (int q = 0; q < 2; q++)  ldsm4(br[q], bbase + q * 1024 + cb);
#pragma unroll
                for (int mt = 0; mt < 4; mt++)
#pragma unroll
                    for (int q = 0; q < 2; q++) {
                        mma16816(acc[mt][2 * q],     ar[mt], &br[q][0]);
                        mma16816(acc[mt][2 * q + 1], ar[mt], &br[q][2]);
                    }
            }
        }
        CP_WAIT0();    // drain before next tile reuses stage buffers

        // epilogue: + bias, store fp16 partial rows
#pragma unroll
        for (int mt = 0; mt < 4; mt++) {
#pragma unroll
            for (int h = 0; h < 2; h++) {
                int row = wm + mt * 16 + (lane >> 2) + h * 8;
                int vv  = s_tok[row];
                if (vv >= 0) {
                    __half* prow = g_part + (size_t)vv * HD + n0;
#pragma unroll
                    for (int nt = 0; nt < 4; nt++) {
                        int c = wn + nt * 8 + (lane & 3) * 2;
                        *(__half2*)(prow + c) = __floats2half2_rn(
                            acc[mt][nt][2 * h]     + s_bias[c],
                            acc[mt][nt][2 * h + 1] + s_bias[c + 1]);
                    }
                }
            }
        }
    }
}

// out[t] = w0 * part[2t] + w1 * part[2t+1]
__global__ void k_combine(float* __restrict__ out) {
    int t = blockIdx.x, tid = threadIdx.x;
    float w0 = g_tws[2 * t], w1 = g_tws[2 * t + 1];
    const __half2* p0 = (const __half2*)(g_part + (size_t)(2 * t) * HD);
    const __half2* p1 = (const __half2*)(g_part + (size_t)(2 * t + 1) * HD);
    float2 a0 = __half22float2(p0[2 * tid]);
    float2 a1 = __half22float2(p0[2 * tid + 1]);
    float2 b0 = __half22float2(p1[2 * tid]);
    float2 b1 = __half22float2(p1[2 * tid + 1]);
    float4 o;
    o.x = w0 * a0.x + w1 * b0.x;
    o.y = w0 * a0.y + w1 * b0.y;
    o.z = w0 * a1.x + w1 * b1.x;
    o.w = w0 * a1.y + w1 * b1.y;
    ((float4*)(out + (size_t)t * HD))[tid] = o;
}

// ---------------------------------------------------------------------------
extern "C" void kernel_launch(void* const* d_in, const int* in_sizes, int n_in,
                              void* d_out, int out_size) {
    const float* x  = (const float*)d_in[0];
    const float* rw = (const float*)d_in[1];
    const float* rb = (const float*)d_in[2];
    const float* ew = (const float*)d_in[3];
    const float* eb = (const float*)d_in[4];
    float* out = (float*)d_out;

    const int DSM = 4 * STAGE;    // 65536
    static int done = 0;
    if (!done) {
        cudaFuncSetAttribute(k_gemm, cudaFuncAttributeMaxDynamicSharedMemorySize, DSM);
        done = 1;
    }

    k_convw<<<(NE * HD * HD) / 1024, 256>>>(ew);
    k_router<<<TT / 32, 256>>>(x, rw, rb);
    k_gemm<<<NCTA, 256, DSM>>>(eb);
    k_combine<<<TT, 256>>>(out);
}

// round 17
// speedup vs baseline: 1.0747x; 1.0363x over previous
#include <cuda_runtime.h>
#include <cuda_fp16.h>
#include <cstdint>

#define TT 8192
#define HD 1024
#define NE 8
#define NKT 32            // 1024 / BK
#define STAGE 16384       // 8KB A + 8KB B per stage (BK=32)
#define NCTA 296          // 2 CTAs/SM x 148 SMs (persistent)

// ---- scratch (device globals; no allocations allowed) ----------------------
__device__ int    g_counts[NE];
__device__ int    g_work;                  // persistent work counter
__device__ int    g_tok[NE * TT];          // slot -> token*2 + choice (-1 pad)
__device__ float  g_tws[2 * TT];           // (token,choice) -> combine weight
__device__ __half g_xh[(size_t)TT * HD];
__device__ __half g_wh[(size_t)NE * HD * HD];
__device__ __half g_part[(size_t)2 * TT * HD];   // fp16 partial rows

// ---- PTX helpers (baseline compute_103-safe) -------------------------------
__device__ __forceinline__ uint32_t smem_u32(const void* p) {
    uint32_t a;
    asm("{ .reg .u64 t; cvta.to.shared.u64 t, %1; cvt.u32.u64 %0, t; }"
        : "=r"(a) : "l"(p));
    return a;
}
#define CP16(dst, src) \
    asm volatile("cp.async.cg.shared.global [%0], [%1], 16;" :: "r"(dst), "l"(src))
#define CP_COMMIT() asm volatile("cp.async.commit_group;" ::: "memory")
#define CP_WAIT2()  asm volatile("cp.async.wait_group 2;" ::: "memory")
#define CP_WAIT0()  asm volatile("cp.async.wait_group 0;" ::: "memory")

__device__ __forceinline__ void ldsm4(uint32_t* r, uint32_t a) {
    asm volatile("ldmatrix.sync.aligned.m8n8.x4.shared.b16 {%0,%1,%2,%3}, [%4];"
                 : "=r"(r[0]), "=r"(r[1]), "=r"(r[2]), "=r"(r[3]) : "r"(a));
}
__device__ __forceinline__ void mma16816(float* c, const uint32_t* a, const uint32_t* b) {
    asm volatile(
        "mma.sync.aligned.m16n8k16.row.col.f32.f16.f16.f32 "
        "{%0,%1,%2,%3}, {%4,%5,%6,%7}, {%8,%9}, {%0,%1,%2,%3};"
        : "+f"(c[0]), "+f"(c[1]), "+f"(c[2]), "+f"(c[3])
        : "r"(a[0]), "r"(a[1]), "r"(a[2]), "r"(a[3]), "r"(b[0]), "r"(b[1]));
}

// swizzled 16B-chunk offset within a tile of 64B rows (4 chunks/row, BK=32)
__device__ __forceinline__ uint32_t swz64(int row, int chunk) {
    return (uint32_t)(row * 64 + ((chunk ^ ((row >> 1) & 3)) << 4));
}

// ---------------------------------------------------------------------------
// expert_w fp32 -> fp16, 8 floats (2 independent float4) per thread for MLP=2.
// (+ zero counters & work counter, block 0)
__global__ void k_convw(const float* __restrict__ w) {
    if (blockIdx.x == 0 && threadIdx.x < NE + 1) {
        if (threadIdx.x < NE) g_counts[threadIdx.x] = 0;
        else g_work = 0;
    }
    size_t i = ((size_t)blockIdx.x * blockDim.x + threadIdx.x) * 8;
    float4 v0 = *(const float4*)(w + i);
    float4 v1 = *(const float4*)(w + i + 4);
    __half2* p = (__half2*)(g_wh + i);
    p[0] = __floats2half2_rn(v0.x, v0.y);
    p[1] = __floats2half2_rn(v0.z, v0.w);
    p[2] = __floats2half2_rn(v1.x, v1.y);
    p[3] = __floats2half2_rn(v1.z, v1.w);
}

// Router + fp16 cast of x. One warp per token (R13 exact — TLP hides latency).
__global__ void k_router(const float* __restrict__ x,
                         const float* __restrict__ rw,
                         const float* __restrict__ rb) {
    __shared__ float s_rw[NE * HD];
    __shared__ float s_rb[NE];
    int tid = threadIdx.x;
    for (int i = tid; i < NE * HD; i += blockDim.x) s_rw[i] = rw[i];
    if (tid < NE) s_rb[tid] = rb[tid];
    __syncthreads();

    int warp = tid >> 5, lane = tid & 31;
    int t = blockIdx.x * 8 + warp;
    const float* xr = x + (size_t)t * HD;

    float xv[32];
#pragma unroll
    for (int i = 0; i < 32; i++) xv[i] = xr[lane + 32 * i];

    __half* xh = g_xh + (size_t)t * HD;
#pragma unroll
    for (int i = 0; i < 32; i++) xh[lane + 32 * i] = __float2half_rn(xv[i]);

    float sc[NE];
#pragma unroll
    for (int e = 0; e < NE; e++) {
        float s = 0.0f;
        const float* wr = s_rw + e * HD;
#pragma unroll
        for (int i = 0; i < 32; i++) s += xv[i] * wr[lane + 32 * i];
#pragma unroll
        for (int o = 16; o > 0; o >>= 1) s += __shfl_xor_sync(0xffffffffu, s, o);
        sc[e] = s + s_rb[e];
    }

    if (lane == 0) {
        int e0 = 0;
#pragma unroll
        for (int e = 1; e < NE; e++) if (sc[e] > sc[e0]) e0 = e;
        int e1 = (e0 == 0) ? 1 : 0;
#pragma unroll
        for (int e = 0; e < NE; e++) if (e != e1 && e != e0 && sc[e] > sc[e1]) e1 = e;

        float d  = __expf(sc[e1] - sc[e0]);   // <= 1, stable
        float w0 = 1.0f / (1.0f + d);
        g_tws[2 * t]     = w0;
        g_tws[2 * t + 1] = 1.0f - w0;
        int p0 = atomicAdd(&g_counts[e0], 1);
        g_tok[e0 * TT + p0] = t * 2;
        int p1 = atomicAdd(&g_counts[e1], 1);
        g_tok[e1 * TT + p1] = t * 2 + 1;
    }
}

// ---------------------------------------------------------------------------
// Persistent grouped GEMM: 296 CTAs, work-stealing over (expert, mtile, ntile).
// Per tile: 128x128, BK=32, 8 warps (2x4), warp tile 64x32, 4-stage cp.async,
// one __syncthreads per ktile, interleaved ldsm/mma (R13 exact). fp16 epilogue.
// ---------------------------------------------------------------------------
__global__ void __launch_bounds__(256, 2)
k_gemm(const float* __restrict__ eb) {
    __shared__ int   s_work;
    __shared__ int   s_tok[128];
    __shared__ float s_bias[128];
    extern __shared__ __align__(128) char dsm[];   // 4 x (A 8KB | B 8KB)

    int tid = threadIdx.x, lane = tid & 31, wid = tid >> 5;

    // per-expert tile prefix sums (registers, identical across threads)
    int pfx[NE + 1];
    pfx[0] = 0;
#pragma unroll
    for (int e = 0; e < NE; e++)
        pfx[e + 1] = pfx[e] + ((g_counts[e] + 127) >> 7);
    int total = pfx[NE] * 8;

    uint32_t sbase = smem_u32(dsm);

    // fixed compute mapping: 2x4 warps, warp tile 64x32
    int wm = (wid >> 2) * 64, wn = (wid & 3) * 32;
    int ha = lane >> 4;
    int hb = (lane >> 3) & 1;
    int sxa = ((lane & 15) >> 1) & 3;
    int sxb = (((((lane >> 4) << 3) + (lane & 7))) >> 1) & 3;
    uint32_t arow = (uint32_t)(wm + (lane & 15)) * 64u;
    uint32_t brow = (uint32_t)(wn + ((lane >> 4) << 3) + (lane & 7)) * 64u;

    // fixed loader mapping pieces
    int lr = tid >> 1;
    int lc = (tid & 1) * 2;
    uint32_t sa0 = swz64(lr, lc), sa1 = swz64(lr, lc + 1);

    for (;;) {
        if (tid == 0) s_work = atomicAdd(&g_work, 1);
        __syncthreads();                       // also protects s_tok reuse
        int s = s_work;
        if (s >= total) break;

        int mg = s >> 3, ntile = s & 7;
        int e = 0;
#pragma unroll
        for (int q = 0; q < NE - 1; q++) if (mg >= pfx[q + 1]) e = q + 1;
        int cnt = g_counts[e];
        int m0  = (mg - pfx[e]) * 128;
        int n0  = ntile * 128;

        if (tid < 128) {
            int m = m0 + tid;
            s_tok[tid]  = (m < cnt) ? g_tok[e * TT + m] : -1;
            s_bias[tid] = eb[e * HD + n0 + tid];
        }
        __syncthreads();

        int v   = s_tok[lr];
        int tok = (v < 0 ? 0 : v) >> 1;
        const char* ga = (const char*)(g_xh + (size_t)tok * HD) + lc * 16;
        const char* gb = (const char*)(g_wh + (size_t)e * HD * HD
                                            + (size_t)(n0 + lr) * HD) + lc * 16;

        auto issue = [&](int kt) {
            uint32_t ab = sbase + (uint32_t)(kt & 3) * STAGE;
            uint32_t bb = ab + 8192u;
            const char* a = ga + kt * 64;
            const char* b = gb + kt * 64;
            CP16(ab + sa0, a);
            CP16(ab + sa1, a + 16);
            CP16(bb + sa0, b);
            CP16(bb + sa1, b + 16);
        };

        float acc[4][4][4];
#pragma unroll
        for (int mt = 0; mt < 4; mt++)
#pragma unroll
            for (int nt = 0; nt < 4; nt++)
#pragma unroll
                for (int j = 0; j < 4; j++) acc[mt][nt][j] = 0.0f;

        issue(0); CP_COMMIT();
        issue(1); CP_COMMIT();
        issue(2); CP_COMMIT();

        for (int kt = 0; kt < NKT; kt++) {
            CP_WAIT2();
            __syncthreads();
            if (kt + 3 < NKT) issue(kt + 3);
            CP_COMMIT();

            uint32_t ab = sbase + (uint32_t)(kt & 3) * STAGE;
            uint32_t bb = ab + 8192u;
            uint32_t abase = ab + arow;
            uint32_t bbase = bb + brow;
#pragma unroll
            for (int ks = 0; ks < 2; ks++) {
                uint32_t ca = (uint32_t)(((ks * 2 + ha) ^ sxa) << 4);
                uint32_t cb = (uint32_t)(((ks * 2 + hb) ^ sxb) << 4);
                uint32_t ar[4][4], br[2][4];
#pragma unroll
                for (int mt = 0; mt < 4; mt++) ldsm4(ar[mt], abase + mt * 1024 + ca);
#pragma unroll
                for (int q = 0; q < 2; q++)  ldsm4(br[q], bbase + q * 1024 + cb);
#pragma unroll
                for (int mt = 0; mt < 4; mt++)
#pragma unroll
                    for (int q = 0; q < 2; q++) {
                        mma16816(acc[mt][2 * q],     ar[mt], &br[q][0]);
                        mma16816(acc[mt][2 * q + 1], ar[mt], &br[q][2]);
                    }
            }
        }
        CP_WAIT0();    // drain before next tile reuses stage buffers

        // epilogue: + bias, store fp16 partial rows
#pragma unroll
        for (int mt = 0; mt < 4; mt++) {
#pragma unroll
            for (int h = 0; h < 2; h++) {
                int row = wm + mt * 16 + (lane >> 2) + h * 8;
                int vv  = s_tok[row];
                if (vv >= 0) {
                    __half* prow = g_part + (size_t)vv * HD + n0;
#pragma unroll
                    for (int nt = 0; nt < 4; nt++) {
                        int c = wn + nt * 8 + (lane & 3) * 2;
                        *(__half2*)(prow + c) = __floats2half2_rn(
                            acc[mt][nt][2 * h]     + s_bias[c],
                            acc[mt][nt][2 * h + 1] + s_bias[c + 1]);
                    }
                }
            }
        }
    }
}

// out[t] = w0 * part[2t] + w1 * part[2t+1]; 4 tokens per block (independent
// streaming iterations -> MLP, fewer waves).
__global__ void __launch_bounds__(256)
k_combine(float* __restrict__ out) {
    int tid = threadIdx.x;
#pragma unroll
    for (int r = 0; r < 4; r++) {
        int t = blockIdx.x * 4 + r;
        float w0 = g_tws[2 * t], w1 = g_tws[2 * t + 1];
        const __half2* p0 = (const __half2*)(g_part + (size_t)(2 * t) * HD);
        const __half2* p1 = (const __half2*)(g_part + (size_t)(2 * t + 1) * HD);
        float2 a0 = __half22float2(p0[2 * tid]);
        float2 a1 = __half22float2(p0[2 * tid + 1]);
        float2 b0 = __half22float2(p1[2 * tid]);
        float2 b1 = __half22float2(p1[2 * tid + 1]);
        float4 o;
        o.x = w0 * a0.x + w1 * b0.x;
        o.y = w0 * a0.y + w1 * b0.y;
        o.z = w0 * a1.x + w1 * b1.x;
        o.w = w0 * a1.y + w1 * b1.y;
        ((float4*)(out + (size_t)t * HD))[tid] = o;
    }
}

// ---------------------------------------------------------------------------
extern "C" void kernel_launch(void* const* d_in, const int* in_sizes, int n_in,
                              void* d_out, int out_size) {
    const float* x  = (const float*)d_in[0];
    const float* rw = (const float*)d_in[1];
    const float* rb = (const float*)d_in[2];
    const float* ew = (const float*)d_in[3];
    const float* eb = (const float*)d_in[4];
    float* out = (float*)d_out;

    const int DSM = 4 * STAGE;    // 65536
    static int done = 0;
    if (!done) {
        cudaFuncSetAttribute(k_gemm, cudaFuncAttributeMaxDynamicSharedMemorySize, DSM);
        done = 1;
    }

    k_convw<<<(NE * HD * HD) / 2048, 256>>>(ew);
    k_router<<<TT / 8, 256>>>(x, rw, rb);
    k_gemm<<<NCTA, 256, DSM>>>(eb);
    k_combine<<<TT / 4, 256>>>(out);
}